// round 12
// baseline (speedup 1.0000x reference)
#include <cuda_runtime.h>
#include <cstdint>

#define NBLK 128
#define TB   512
#define B_   512
#define S_   512
#define T_   511
#define H_   256
#define NTY  128
#define NG   1792
#define HP   260
#define GP   116
#define GTSF 7424            // floats per gts buffer (29696 B)

// ---- scan-phase smem ----
#define OFF_WF   0           // 14 nf x 8 kf2 x 32 lanes x uint4 = 57344 B
#define OFF_AF   57344       // 4 mt x 16 kf x 32 lanes x uint4 = 32768 B
#define OFF_GTS  90112       // 2 x (64 x 116 x 4) = 59392 B
// ---- phase-2 smem ----
#define OFF_WFL 0
#define OFF_H2  131072
#define SMEM_BYTES 197632

__device__ __align__(16) float g_P[NTY * NG];
__device__ __align__(16) uint32_t g_hx[2][B_ * H_ / 2];   // bf16x2-packed h exchange
__device__ unsigned g_cnt_full = 0;
__device__ unsigned g_gen_full = 0;
__device__ __align__(64) unsigned g_flag[8 * 16];          // per-group arrival flags

__device__ __forceinline__ unsigned f2tf32(float x) {
    unsigned u;
    asm("cvt.rna.tf32.f32 %0, %1;" : "=r"(u) : "f"(x));
    return u;
}
__device__ __forceinline__ float tf(float x) { return __uint_as_float(f2tf32(x)); }

__device__ __forceinline__ unsigned packbf(float lo, float hi) {
    unsigned r;
    asm("cvt.rn.bf16x2.f32 %0, %1, %2;" : "=r"(r) : "f"(hi), "f"(lo));
    return r;
}

__device__ __forceinline__ void mma16(float* d, uint4 a, unsigned b0, unsigned b1) {
    asm volatile(
        "mma.sync.aligned.m16n8k16.row.col.f32.bf16.bf16.f32 "
        "{%0,%1,%2,%3}, {%4,%5,%6,%7}, {%8,%9}, {%0,%1,%2,%3};"
        : "+f"(d[0]), "+f"(d[1]), "+f"(d[2]), "+f"(d[3])
        : "r"(a.x), "r"(a.y), "r"(a.z), "r"(a.w), "r"(b0), "r"(b1));
}
__device__ __forceinline__ void mma8(float* d, unsigned a0, unsigned a1, unsigned a2, unsigned a3,
                                     unsigned b0, unsigned b1) {
    asm volatile(
        "mma.sync.aligned.m16n8k8.row.col.f32.tf32.tf32.f32 "
        "{%0,%1,%2,%3}, {%4,%5,%6,%7}, {%8,%9}, {%0,%1,%2,%3};"
        : "+f"(d[0]), "+f"(d[1]), "+f"(d[2]), "+f"(d[3])
        : "r"(a0), "r"(a1), "r"(a2), "r"(a3), "r"(b0), "r"(b1));
}

__device__ __forceinline__ float sigf(float x)   { return __fdividef(1.0f, 1.0f + __expf(-x)); }
__device__ __forceinline__ float tanhx(float x)  { return 1.0f - __fdividef(2.0f, __expf(2.0f * x) + 1.0f); }
__device__ __forceinline__ float softplusf(float x) {
    return x > 15.0f ? x : __logf(1.0f + __expf(x));
}

__device__ __forceinline__ void full_barrier() {
    __syncthreads();
    if (threadIdx.x == 0) {
        volatile unsigned* genp = &g_gen_full;
        unsigned gen = *genp;
        __threadfence();
        if (atomicAdd(&g_cnt_full, 1u) == NBLK - 1u) {
            g_cnt_full = 0u;
            __threadfence();
            *genp = gen + 1u;
        } else {
            while (*genp == gen) {}
        }
        __threadfence();
    }
    __syncthreads();
}

__global__ void __launch_bounds__(TB, 1)
ctlstm_kernel(const int* __restrict__ types, const float* __restrict__ dtime,
              const float* __restrict__ emb, const float* __restrict__ Wc,
              const float* __restrict__ bc, const float* __restrict__ Wl,
              const float* __restrict__ bl, float* __restrict__ out)
{
    extern __shared__ __align__(1024) char smem[];
    const int tid  = threadIdx.x;
    const int wid  = tid >> 5;
    const int lane = tid & 31;
    const int gid  = lane >> 2;
    const int tig  = lane & 3;
    const int bb   = blockIdx.x >> 4;   // batch tile 0..7 (64 rows)
    const int hb   = blockIdx.x & 15;   // hidden tile 0..15 (16 hids)

    float* intens = out;
    float* h_out  = out + (size_t)B_ * T_ * NTY;
    const size_t CH = (size_t)T_ * B_ * H_;
    float* c_out  = h_out + CH;
    float* cb_out = h_out + 2 * CH;
    float* de_out = h_out + 3 * CH;
    float* o_out  = h_out + 4 * CH;

    const unsigned fbase = g_flag[bb * 16 + hb];

    // ---- Phase 0a: pack W_h slice -> bf16 B fragments, permuted k layout ----
    // slot (kf, kh, t4) holds k-pair w = kf*8 + kh*4 + ((t4 - (kf&3)) & 3); k = 2w, 2w+1
    for (int e = tid; e < 14 * 8 * 32; e += TB) {
        int nf  = e >> 8;
        int kf2 = (e >> 5) & 7;
        int ln  = e & 31;
        int g8  = ln >> 2, t4 = ln & 3;
        int q = nf >> 1;
        int n = q * H_ + hb * 16 + (nf & 1) * 8 + g8;
        const float* Wh = Wc + (size_t)H_ * NG + n;
        unsigned bw[4];
        #pragma unroll
        for (int kk = 0; kk < 2; kk++) {
            int kf = 2 * kf2 + kk;
            #pragma unroll
            for (int kh = 0; kh < 2; kh++) {
                int w  = kf * 8 + kh * 4 + ((t4 - (kf & 3)) & 3);
                int k0 = 2 * w;
                bw[kk * 2 + kh] = packbf(Wh[(size_t)k0 * NG], Wh[(size_t)(k0 + 1) * NG]);
            }
        }
        ((uint4*)(smem + OFF_WF))[e] = make_uint4(bw[0], bw[1], bw[2], bw[3]);
    }
    // ---- Phase 0b: P[type] = emb_table[type] @ W_x + b_cell (1 type / block) ----
    {
        float* scr = (float*)(smem + OFF_AF);
        int ty = blockIdx.x;
        if (tid < H_) scr[tid] = emb[ty * H_ + tid];
        __syncthreads();
        for (int n = tid; n < NG; n += TB) {
            float acc = bc[n];
            #pragma unroll 8
            for (int k = 0; k < H_; k++) acc = fmaf(scr[k], Wc[(size_t)k * NG + n], acc);
            g_P[ty * NG + n] = acc;
        }
        __syncthreads();
    }
    full_barrier();

    // ---- Phase 1: sequential CT-LSTM scan ----
    const int wl  = wid & 7;            // tile persona (shared by warp pair w, w+8)
    const int kh4 = (wid >> 3) * 4;     // split-K: kf2 range [kh4, kh4+4)
    const int mw  = wl & 1;             // M half
    const int nw  = wl >> 1;            // N quarter
    const int rb2 = tid >> 3;           // row 0..63
    const int hp  = tid & 7;            // hid pair 0..7
    const int b2  = bb * 64 + rb2;
    const int hid0 = hb * 16 + hp * 2;

    // staging map: warp covers rows mt*16 + {2q, 2q+1, 2q+8, 2q+9}
    const int s_mt   = wid >> 2;
    const int s_q    = wid & 3;
    const int s_rr   = lane >> 3;
    const int s_i    = lane & 7;
    const int s_gid  = 2 * s_q + (s_rr & 1);
    const int s_half = s_rr >> 1;
    const int s_row  = s_mt * 16 + s_half * 8 + s_gid;
    const int s_sq   = s_i >> 1;
    uint32_t* AFw = (uint32_t*)(smem + OFF_AF);
    const uint32_t s_base = s_mt * 2048 + s_gid * 16 + (s_i & 1) * 2 + s_half + s_sq * 128;

    float cst0 = 0.f, cst1 = 0.f, cbst0 = 0.f, cbst1 = 0.f;

    unsigned* const myflag = g_flag + bb * 16 + hb;
    unsigned* const grpflags = g_flag + bb * 16;

    for (int t = 0; t < T_; t++) {
        // ---- prefetch gate-independent operands (issued BEFORE the wait) ----
        int   ty = __ldg(types + (size_t)b2 * S_ + t);
        float dt = __ldg(dtime + (size_t)b2 * S_ + t + 1);
        float2 pg[7];
        {
            const float2* Pr = (const float2*)(g_P + (size_t)ty * NG + hid0);
            #pragma unroll
            for (int q = 0; q < 7; q++) pg[q] = __ldg(Pr + q * (H_ / 2));
        }

        if (t > 0) {
            // ---- wait: ONE polling warp, 16 parallel lanes ----
            if (wid == 0 && lane < 16) {
                const unsigned tgt = fbase + (unsigned)t;
                unsigned v;
                do {
                    asm volatile("ld.acquire.gpu.global.u32 %0, [%1];"
                                 : "=r"(v) : "l"(grpflags + lane) : "memory");
                } while ((int)(v - tgt) < 0);
            }
            __syncthreads();

            // ---- stage bf16 h_{t-1} -> A fragments (conflict-free scatter) ----
            {
                const uint4* src = (const uint4*)(g_hx[(t - 1) & 1]
                                                  + (size_t)(bb * 64 + s_row) * 128);
                #pragma unroll
                for (int j = 0; j < 4; j++) {
                    uint4 v = __ldcg(src + s_i + 8 * j);
                    uint32_t a = s_base + j * 512;
                    AFw[a + (((s_sq + 0) & 3) << 2)] = v.x;
                    AFw[a + (((s_sq + 1) & 3) << 2)] = v.y;
                    AFw[a + (((s_sq + 2) & 3) << 2)] = v.z;
                    AFw[a + (((s_sq + 3) & 3) << 2)] = v.w;
                }
            }
            __syncthreads();

            // ---- gates = h @ W_h : split-K, 16 warps, pair (w, w+8) shares tile ----
            {
                float acc[2][4][4];
                #pragma unroll
                for (int m = 0; m < 2; m++)
                    #pragma unroll
                    for (int f = 0; f < 4; f++)
                        #pragma unroll
                        for (int r2 = 0; r2 < 4; r2++) acc[m][f][r2] = 0.f;
                const uint4* AFp = (const uint4*)(smem + OFF_AF) + (mw * 2 * 16) * 32 + lane;
                const uint4* WFp = (const uint4*)(smem + OFF_WF) + (nw * 4 * 8) * 32 + lane;
                #pragma unroll
                for (int kk = 0; kk < 4; kk++) {
                    int kf2 = kh4 + kk;
                    uint4 bv[4];
                    #pragma unroll
                    for (int f = 0; f < 4; f++) bv[f] = WFp[(f * 8 + kf2) * 32];
                    uint4 a0e = AFp[(2 * kf2) * 32];
                    uint4 a0o = AFp[(2 * kf2 + 1) * 32];
                    uint4 a1e = AFp[(16 + 2 * kf2) * 32];
                    uint4 a1o = AFp[(16 + 2 * kf2 + 1) * 32];
                    #pragma unroll
                    for (int f = 0; f < 4; f++) {
                        mma16(acc[0][f], a0e, bv[f].x, bv[f].y);
                        mma16(acc[1][f], a1e, bv[f].x, bv[f].y);
                        mma16(acc[0][f], a0o, bv[f].z, bv[f].w);
                        mma16(acc[1][f], a1o, bv[f].z, bv[f].w);
                    }
                }
                float* g = (float*)(smem + OFF_GTS) + (wid >> 3) * GTSF;
                #pragma unroll
                for (int m = 0; m < 2; m++) {
                    #pragma unroll
                    for (int f = 0; f < 4; f++) {
                        int fg = nw * 4 + f;
                        if (fg < 14) {
                            int c  = fg * 8 + 2 * tig;
                            int r0 = mw * 32 + m * 16 + gid;
                            *(float2*)(g + r0 * GP + c)       = make_float2(acc[m][f][0], acc[m][f][1]);
                            *(float2*)(g + (r0 + 8) * GP + c) = make_float2(acc[m][f][2], acc[m][f][3]);
                        }
                    }
                }
            }
            __syncthreads();
        }

        // ---- elementwise CT-LSTM update (1 row x 2 hids per thread) ----
        float g0[7], g1[7];
        if (t > 0) {
            const float* gr0 = (const float*)(smem + OFF_GTS) + rb2 * GP + hp * 2;
            const float* gr1 = gr0 + GTSF;
            #pragma unroll
            for (int q = 0; q < 7; q++) {
                float2 v0 = *(const float2*)(gr0 + q * 16);
                float2 v1 = *(const float2*)(gr1 + q * 16);
                g0[q] = (pg[q].x + v0.x) + v1.x;
                g1[q] = (pg[q].y + v0.y) + v1.y;
            }
        } else {
            #pragma unroll
            for (int q = 0; q < 7; q++) { g0[q] = pg[q].x; g1[q] = pg[q].y; }
        }
        float hn0, hn1, ci0, ci1, cb0, cb1, de0, de1, ov0, ov1;
        {
            float iv = sigf(g0[0]), fv = sigf(g0[1]), zv = tanhx(g0[2]);
            ov0 = sigf(g0[3]);
            float ib = sigf(g0[4]), fb = sigf(g0[5]);
            de0 = softplusf(g0[6]);
            ci0 = fv * cst0 + iv * zv;
            cb0 = fb * cbst0 + ib * zv;
            float ct = cb0 + (ci0 - cb0) * __expf(-de0 * dt);
            hn0 = ov0 * tanhx(ct);
            cst0 = ct; cbst0 = cb0;
        }
        {
            float iv = sigf(g1[0]), fv = sigf(g1[1]), zv = tanhx(g1[2]);
            ov1 = sigf(g1[3]);
            float ib = sigf(g1[4]), fb = sigf(g1[5]);
            de1 = softplusf(g1[6]);
            ci1 = fv * cst1 + iv * zv;
            cb1 = fb * cbst1 + ib * zv;
            float ct = cb1 + (ci1 - cb1) * __expf(-de1 * dt);
            hn1 = ov1 * tanhx(ct);
            cst1 = ct; cbst1 = cb1;
        }
        // critical-path: packed h to exchange scratch
        g_hx[t & 1][(size_t)b2 * 128 + hb * 8 + hp] = packbf(hn0, hn1);
        __syncthreads();

        // ---- arrive (release), then overlap output stores with peer skew ----
        if (tid == 0) {
            asm volatile("st.release.gpu.global.u32 [%0], %1;"
                         :: "l"(myflag), "r"(fbase + (unsigned)t + 1u) : "memory");
        }
        {
            size_t idx = (size_t)t * (B_ * H_) + (size_t)b2 * H_ + hid0;
            *(float2*)(h_out  + idx) = make_float2(hn0, hn1);
            *(float2*)(c_out  + idx) = make_float2(ci0, ci1);
            *(float2*)(cb_out + idx) = make_float2(cb0, cb1);
            *(float2*)(de_out + idx) = make_float2(de0, de1);
            *(float2*)(o_out  + idx) = make_float2(ov0, ov1);
        }
        // wait deferred to top of next iteration (after its prefetch)
    }

    full_barrier();

    // ---- Phase 2: intensity = softplus(h_out @ W_lam + b_lam), tf32 HMMA ----
    {
        float2* WfL = (float2*)(smem + OFF_WFL);
        float*  h2  = (float*)(smem + OFF_H2);
        const int mwp = wid & 3, nwp = wid >> 2;
        for (int e = tid; e < 16 * 32 * 32; e += TB) {
            int nf = e >> 10, kf = (e >> 5) & 31, ln = e & 31;
            int g8 = ln >> 2, t4 = ln & 3;
            int n = nf * 8 + g8;
            int k = kf * 8 + t4;
            float x = Wl[(size_t)k * NTY + n];
            float y = Wl[(size_t)(k + 4) * NTY + n];
            WfL[e] = make_float2(tf(x), tf(y));
        }
        __syncthreads();

        const int NTILE = (T_ * B_) / 64;   // 4088
        for (int mt = blockIdx.x; mt < NTILE; mt += NBLK) {
            int r0t = mt * 64;
            int tt = r0t >> 9;
            int b0 = r0t & 511;
            {
                int row = tid >> 3, inner = tid & 7;
                const float4* src = (const float4*)(h_out + (size_t)tt * (B_ * H_)
                                                    + (size_t)(b0 + row) * H_);
                float* dst = h2 + row * HP;
                #pragma unroll
                for (int j = 0; j < 8; j++) {
                    int c4 = inner + 8 * j;
                    float4 v = __ldcg(src + c4);
                    v.x = tf(v.x); v.y = tf(v.y); v.z = tf(v.z); v.w = tf(v.w);
                    *(float4*)(dst + c4 * 4) = v;
                }
            }
            __syncthreads();
            float d[4][4];
            #pragma unroll
            for (int q = 0; q < 4; q++)
                #pragma unroll
                for (int r2 = 0; r2 < 4; r2++) d[q][r2] = 0.f;
            const float*  hrow = h2 + (mwp * 16 + gid) * HP + tig;
            const float2* wb   = WfL + (size_t)(nwp * 4) * 1024 + lane;
            #pragma unroll 2
            for (int kf = 0; kf < 32; kf++) {
                unsigned a0 = __float_as_uint(hrow[kf * 8]);
                unsigned a1 = __float_as_uint(hrow[kf * 8 + 8 * HP]);
                unsigned a2 = __float_as_uint(hrow[kf * 8 + 4]);
                unsigned a3 = __float_as_uint(hrow[kf * 8 + 8 * HP + 4]);
                #pragma unroll
                for (int q = 0; q < 4; q++) {
                    float2 bv = wb[(q * 32 + kf) * 32];
                    mma8(d[q], a0, a1, a2, a3, __float_as_uint(bv.x), __float_as_uint(bv.y));
                }
            }
            int rl = mwp * 16 + gid;
            #pragma unroll
            for (int q = 0; q < 4; q++) {
                int n0 = (nwp * 4 + q) * 8 + 2 * tig;
                float bv0 = __ldg(bl + n0), bv1 = __ldg(bl + n0 + 1);
                size_t base = (size_t)(b0 + rl) * (T_ * NTY) + (size_t)tt * NTY + n0;
                *(float2*)(intens + base) =
                    make_float2(softplusf(d[q][0] + bv0), softplusf(d[q][1] + bv1));
                size_t base2 = base + (size_t)8 * (T_ * NTY);
                *(float2*)(intens + base2) =
                    make_float2(softplusf(d[q][2] + bv0), softplusf(d[q][3] + bv1));
            }
            __syncthreads();
        }
    }
}

extern "C" void kernel_launch(void* const* d_in, const int* in_sizes, int n_in,
                              void* d_out, int out_size) {
    const int*   types = (const int*)d_in[0];
    const float* dtime = (const float*)d_in[1];
    const float* emb   = (const float*)d_in[2];
    const float* Wc    = (const float*)d_in[3];
    const float* bc    = (const float*)d_in[4];
    const float* Wl    = (const float*)d_in[5];
    const float* bl    = (const float*)d_in[6];
    cudaFuncSetAttribute(ctlstm_kernel, cudaFuncAttributeMaxDynamicSharedMemorySize, SMEM_BYTES);
    ctlstm_kernel<<<NBLK, TB, SMEM_BYTES>>>(types, dtime, emb, Wc, bc, Wl, bl, (float*)d_out);
}

// round 13
// speedup vs baseline: 1.1499x; 1.1499x over previous
#include <cuda_runtime.h>
#include <cstdint>

#define NBLK 128
#define TB   512
#define B_   512
#define S_   512
#define T_   511
#define H_   256
#define NTY  128
#define NG   1792
#define HP   260
#define GP   116

// ---- scan-phase smem ----
#define OFF_WF  0            // 14 nf x 8 kf2 x 32 lanes x uint4 = 57344 B
#define OFF_AF  57344        // 4 mt x 16 kf x 32 lanes x uint4 = 32768 B
#define OFF_GTS 90112        // 64 x 116 x 4 = 29696 B
// ---- phase-2 smem ----
#define OFF_WFL 0
#define OFF_H2  131072
#define SMEM_BYTES 197632

__device__ __align__(16) float g_P[NTY * NG];
__device__ __align__(16) uint32_t g_hx[2][B_ * H_ / 2];   // bf16x2-packed h exchange
__device__ unsigned g_cnt_full = 0;
__device__ unsigned g_gen_full = 0;
__device__ __align__(64) unsigned g_flag[8 * 16];          // per-group arrival flags

__device__ __forceinline__ unsigned f2tf32(float x) {
    unsigned u;
    asm("cvt.rna.tf32.f32 %0, %1;" : "=r"(u) : "f"(x));
    return u;
}
__device__ __forceinline__ float tf(float x) { return __uint_as_float(f2tf32(x)); }

__device__ __forceinline__ unsigned packbf(float lo, float hi) {
    unsigned r;
    asm("cvt.rn.bf16x2.f32 %0, %1, %2;" : "=r"(r) : "f"(hi), "f"(lo));
    return r;
}

__device__ __forceinline__ void mma16(float* d, uint4 a, unsigned b0, unsigned b1) {
    asm volatile(
        "mma.sync.aligned.m16n8k16.row.col.f32.bf16.bf16.f32 "
        "{%0,%1,%2,%3}, {%4,%5,%6,%7}, {%8,%9}, {%0,%1,%2,%3};"
        : "+f"(d[0]), "+f"(d[1]), "+f"(d[2]), "+f"(d[3])
        : "r"(a.x), "r"(a.y), "r"(a.z), "r"(a.w), "r"(b0), "r"(b1));
}
__device__ __forceinline__ void mma8(float* d, unsigned a0, unsigned a1, unsigned a2, unsigned a3,
                                     unsigned b0, unsigned b1) {
    asm volatile(
        "mma.sync.aligned.m16n8k8.row.col.f32.tf32.tf32.f32 "
        "{%0,%1,%2,%3}, {%4,%5,%6,%7}, {%8,%9}, {%0,%1,%2,%3};"
        : "+f"(d[0]), "+f"(d[1]), "+f"(d[2]), "+f"(d[3])
        : "r"(a0), "r"(a1), "r"(a2), "r"(a3), "r"(b0), "r"(b1));
}

// hardware tanh (MUFU.TANH): 1 MUFU op, |err| ~1e-5 abs
__device__ __forceinline__ float tanhfast(float x) {
    float r;
    asm("tanh.approx.f32 %0, %1;" : "=f"(r) : "f"(x));
    return r;
}
__device__ __forceinline__ float sigf(float x) {
    return fmaf(0.5f, tanhfast(0.5f * x), 0.5f);
}
__device__ __forceinline__ float tanhx(float x) { return tanhfast(x); }
__device__ __forceinline__ float softplusf(float x) {
    return x > 15.0f ? x : __logf(1.0f + __expf(x));
}

__device__ __forceinline__ void full_barrier() {
    __syncthreads();
    if (threadIdx.x == 0) {
        volatile unsigned* genp = &g_gen_full;
        unsigned gen = *genp;
        __threadfence();
        if (atomicAdd(&g_cnt_full, 1u) == NBLK - 1u) {
            g_cnt_full = 0u;
            __threadfence();
            *genp = gen + 1u;
        } else {
            while (*genp == gen) {}
        }
        __threadfence();
    }
    __syncthreads();
}

__global__ void __launch_bounds__(TB, 1)
ctlstm_kernel(const int* __restrict__ types, const float* __restrict__ dtime,
              const float* __restrict__ emb, const float* __restrict__ Wc,
              const float* __restrict__ bc, const float* __restrict__ Wl,
              const float* __restrict__ bl, float* __restrict__ out)
{
    extern __shared__ __align__(1024) char smem[];
    const int tid  = threadIdx.x;
    const int wid  = tid >> 5;
    const int lane = tid & 31;
    const int gid  = lane >> 2;
    const int tig  = lane & 3;
    const int bb   = blockIdx.x >> 4;   // batch tile 0..7 (64 rows)
    const int hb   = blockIdx.x & 15;   // hidden tile 0..15 (16 hids)

    float* intens = out;
    float* h_out  = out + (size_t)B_ * T_ * NTY;
    const size_t CH = (size_t)T_ * B_ * H_;
    float* c_out  = h_out + CH;
    float* cb_out = h_out + 2 * CH;
    float* de_out = h_out + 3 * CH;
    float* o_out  = h_out + 4 * CH;

    const unsigned fbase = g_flag[bb * 16 + hb];

    // ---- Phase 0a: pack W_h slice -> bf16 B fragments, permuted k layout ----
    // slot (kf, kh, t4) holds k-pair w = kf*8 + kh*4 + ((t4 - (kf&3)) & 3); k = 2w, 2w+1
    for (int e = tid; e < 14 * 8 * 32; e += TB) {
        int nf  = e >> 8;
        int kf2 = (e >> 5) & 7;
        int ln  = e & 31;
        int g8  = ln >> 2, t4 = ln & 3;
        int q = nf >> 1;
        int n = q * H_ + hb * 16 + (nf & 1) * 8 + g8;
        const float* Wh = Wc + (size_t)H_ * NG + n;
        unsigned bw[4];
        #pragma unroll
        for (int kk = 0; kk < 2; kk++) {
            int kf = 2 * kf2 + kk;
            #pragma unroll
            for (int kh = 0; kh < 2; kh++) {
                int w  = kf * 8 + kh * 4 + ((t4 - (kf & 3)) & 3);
                int k0 = 2 * w;
                bw[kk * 2 + kh] = packbf(Wh[(size_t)k0 * NG], Wh[(size_t)(k0 + 1) * NG]);
            }
        }
        ((uint4*)(smem + OFF_WF))[e] = make_uint4(bw[0], bw[1], bw[2], bw[3]);
    }
    // ---- Phase 0b: P[type] = emb_table[type] @ W_x + b_cell (1 type / block) ----
    {
        float* scr = (float*)(smem + OFF_AF);
        int ty = blockIdx.x;
        if (tid < H_) scr[tid] = emb[ty * H_ + tid];
        __syncthreads();
        for (int n = tid; n < NG; n += TB) {
            float acc = bc[n];
            #pragma unroll 8
            for (int k = 0; k < H_; k++) acc = fmaf(scr[k], Wc[(size_t)k * NG + n], acc);
            g_P[ty * NG + n] = acc;
        }
        __syncthreads();
    }
    full_barrier();

    // ---- Phase 1: sequential CT-LSTM scan ----
    const int mw = wid & 1;             // M half
    const int nw = wid >> 1;            // N quarter
    const int rb2 = tid >> 3;           // row 0..63
    const int hp  = tid & 7;            // hid pair 0..7
    const int b2  = bb * 64 + rb2;
    const int hid0 = hb * 16 + hp * 2;

    // staging map: warp covers rows mt*16 + {2q, 2q+1, 2q+8, 2q+9}
    const int s_mt   = wid >> 2;
    const int s_q    = wid & 3;
    const int s_rr   = lane >> 3;
    const int s_i    = lane & 7;
    const int s_gid  = 2 * s_q + (s_rr & 1);
    const int s_half = s_rr >> 1;
    const int s_row  = s_mt * 16 + s_half * 8 + s_gid;
    const int s_sq   = s_i >> 1;
    uint32_t* AFw = (uint32_t*)(smem + OFF_AF);
    const uint32_t s_base = s_mt * 2048 + s_gid * 16 + (s_i & 1) * 2 + s_half + s_sq * 128;

    float cst0 = 0.f, cst1 = 0.f, cbst0 = 0.f, cbst1 = 0.f;

    unsigned* const myflag = g_flag + bb * 16 + hb;
    unsigned* const grpflags = g_flag + bb * 16;

    for (int t = 0; t < T_; t++) {
        // ---- prefetch gate-independent operands (issued BEFORE the wait) ----
        int   ty = __ldg(types + (size_t)b2 * S_ + t);
        float dt = __ldg(dtime + (size_t)b2 * S_ + t + 1);
        float2 pg[7];
        {
            const float2* Pr = (const float2*)(g_P + (size_t)ty * NG + hid0);
            #pragma unroll
            for (int q = 0; q < 7; q++) pg[q] = __ldg(Pr + q * (H_ / 2));
        }

        if (t > 0) {
            // ---- wait: ONE polling warp, 16 parallel lanes ----
            if (wid == 0 && lane < 16) {
                const unsigned tgt = fbase + (unsigned)t;
                unsigned v;
                do {
                    asm volatile("ld.acquire.gpu.global.u32 %0, [%1];"
                                 : "=r"(v) : "l"(grpflags + lane) : "memory");
                } while ((int)(v - tgt) < 0);
            }
            __syncthreads();

            // ---- stage bf16 h_{t-1} -> A fragments (conflict-free scatter) ----
            {
                const uint4* src = (const uint4*)(g_hx[(t - 1) & 1]
                                                  + (size_t)(bb * 64 + s_row) * 128);
                #pragma unroll
                for (int j = 0; j < 4; j++) {
                    uint4 v = __ldcg(src + s_i + 8 * j);
                    uint32_t a = s_base + j * 512;
                    AFw[a + (((s_sq + 0) & 3) << 2)] = v.x;
                    AFw[a + (((s_sq + 1) & 3) << 2)] = v.y;
                    AFw[a + (((s_sq + 2) & 3) << 2)] = v.z;
                    AFw[a + (((s_sq + 3) & 3) << 2)] = v.w;
                }
            }
            __syncthreads();

            // ---- gates = h @ W_h : warps 0..7, each m32 x n32, bf16 m16n8k16 ----
            if (wid < 8) {
                float acc[2][4][4];
                #pragma unroll
                for (int m = 0; m < 2; m++)
                    #pragma unroll
                    for (int f = 0; f < 4; f++)
                        #pragma unroll
                        for (int r2 = 0; r2 < 4; r2++) acc[m][f][r2] = 0.f;
                const uint4* AFp = (const uint4*)(smem + OFF_AF) + (mw * 2 * 16) * 32 + lane;
                const uint4* WFp = (const uint4*)(smem + OFF_WF) + (nw * 4 * 8) * 32 + lane;
                #pragma unroll
                for (int kf2 = 0; kf2 < 8; kf2++) {
                    uint4 bv[4];
                    #pragma unroll
                    for (int f = 0; f < 4; f++) bv[f] = WFp[(f * 8 + kf2) * 32];
                    uint4 a0e = AFp[(2 * kf2) * 32];
                    uint4 a0o = AFp[(2 * kf2 + 1) * 32];
                    uint4 a1e = AFp[(16 + 2 * kf2) * 32];
                    uint4 a1o = AFp[(16 + 2 * kf2 + 1) * 32];
                    #pragma unroll
                    for (int f = 0; f < 4; f++) {
                        mma16(acc[0][f], a0e, bv[f].x, bv[f].y);
                        mma16(acc[1][f], a1e, bv[f].x, bv[f].y);
                        mma16(acc[0][f], a0o, bv[f].z, bv[f].w);
                        mma16(acc[1][f], a1o, bv[f].z, bv[f].w);
                    }
                }
                float* g = (float*)(smem + OFF_GTS);
                #pragma unroll
                for (int m = 0; m < 2; m++) {
                    #pragma unroll
                    for (int f = 0; f < 4; f++) {
                        int fg = nw * 4 + f;
                        if (fg < 14) {
                            int c  = fg * 8 + 2 * tig;
                            int r0 = mw * 32 + m * 16 + gid;
                            *(float2*)(g + r0 * GP + c)       = make_float2(acc[m][f][0], acc[m][f][1]);
                            *(float2*)(g + (r0 + 8) * GP + c) = make_float2(acc[m][f][2], acc[m][f][3]);
                        }
                    }
                }
            }
            __syncthreads();
        }

        // ---- elementwise CT-LSTM update (1 row x 2 hids per thread) ----
        float g0[7], g1[7];
        if (t > 0) {
            const float* gr = (const float*)(smem + OFF_GTS) + rb2 * GP + hp * 2;
            #pragma unroll
            for (int q = 0; q < 7; q++) {
                float2 v = *(const float2*)(gr + q * 16);
                g0[q] = v.x + pg[q].x;
                g1[q] = v.y + pg[q].y;
            }
        } else {
            #pragma unroll
            for (int q = 0; q < 7; q++) { g0[q] = pg[q].x; g1[q] = pg[q].y; }
        }
        float hn0, hn1, ci0, ci1, cb0, cb1, de0, de1, ov0, ov1;
        {
            float iv = sigf(g0[0]), fv = sigf(g0[1]), zv = tanhx(g0[2]);
            ov0 = sigf(g0[3]);
            float ib = sigf(g0[4]), fb = sigf(g0[5]);
            de0 = softplusf(g0[6]);
            ci0 = fv * cst0 + iv * zv;
            cb0 = fb * cbst0 + ib * zv;
            float ct = cb0 + (ci0 - cb0) * __expf(-de0 * dt);
            hn0 = ov0 * tanhx(ct);
            cst0 = ct; cbst0 = cb0;
        }
        {
            float iv = sigf(g1[0]), fv = sigf(g1[1]), zv = tanhx(g1[2]);
            ov1 = sigf(g1[3]);
            float ib = sigf(g1[4]), fb = sigf(g1[5]);
            de1 = softplusf(g1[6]);
            ci1 = fv * cst1 + iv * zv;
            cb1 = fb * cbst1 + ib * zv;
            float ct = cb1 + (ci1 - cb1) * __expf(-de1 * dt);
            hn1 = ov1 * tanhx(ct);
            cst1 = ct; cbst1 = cb1;
        }
        // critical-path: packed h to exchange scratch
        g_hx[t & 1][(size_t)b2 * 128 + hb * 8 + hp] = packbf(hn0, hn1);
        __syncthreads();

        // ---- arrive (release), then overlap output stores with peer skew ----
        if (tid == 0) {
            asm volatile("st.release.gpu.global.u32 [%0], %1;"
                         :: "l"(myflag), "r"(fbase + (unsigned)t + 1u) : "memory");
        }
        {
            size_t idx = (size_t)t * (B_ * H_) + (size_t)b2 * H_ + hid0;
            *(float2*)(h_out  + idx) = make_float2(hn0, hn1);
            *(float2*)(c_out  + idx) = make_float2(ci0, ci1);
            *(float2*)(cb_out + idx) = make_float2(cb0, cb1);
            *(float2*)(de_out + idx) = make_float2(de0, de1);
            *(float2*)(o_out  + idx) = make_float2(ov0, ov1);
        }
        // wait deferred to top of next iteration (after its prefetch)
    }

    full_barrier();

    // ---- Phase 2: intensity = softplus(h_out @ W_lam + b_lam), tf32 HMMA ----
    {
        float2* WfL = (float2*)(smem + OFF_WFL);
        float*  h2  = (float*)(smem + OFF_H2);
        const int mwp = wid & 3, nwp = wid >> 2;
        for (int e = tid; e < 16 * 32 * 32; e += TB) {
            int nf = e >> 10, kf = (e >> 5) & 31, ln = e & 31;
            int g8 = ln >> 2, t4 = ln & 3;
            int n = nf * 8 + g8;
            int k = kf * 8 + t4;
            float x = Wl[(size_t)k * NTY + n];
            float y = Wl[(size_t)(k + 4) * NTY + n];
            WfL[e] = make_float2(tf(x), tf(y));
        }
        __syncthreads();

        const int NTILE = (T_ * B_) / 64;   // 4088
        for (int mt = blockIdx.x; mt < NTILE; mt += NBLK) {
            int r0t = mt * 64;
            int tt = r0t >> 9;
            int b0 = r0t & 511;
            {
                int row = tid >> 3, inner = tid & 7;
                const float4* src = (const float4*)(h_out + (size_t)tt * (B_ * H_)
                                                    + (size_t)(b0 + row) * H_);
                float* dst = h2 + row * HP;
                #pragma unroll
                for (int j = 0; j < 8; j++) {
                    int c4 = inner + 8 * j;
                    float4 v = __ldcg(src + c4);
                    v.x = tf(v.x); v.y = tf(v.y); v.z = tf(v.z); v.w = tf(v.w);
                    *(float4*)(dst + c4 * 4) = v;
                }
            }
            __syncthreads();
            float d[4][4];
            #pragma unroll
            for (int q = 0; q < 4; q++)
                #pragma unroll
                for (int r2 = 0; r2 < 4; r2++) d[q][r2] = 0.f;
            const float*  hrow = h2 + (mwp * 16 + gid) * HP + tig;
            const float2* wb   = WfL + (size_t)(nwp * 4) * 1024 + lane;
            #pragma unroll 2
            for (int kf = 0; kf < 32; kf++) {
                unsigned a0 = __float_as_uint(hrow[kf * 8]);
                unsigned a1 = __float_as_uint(hrow[kf * 8 + 8 * HP]);
                unsigned a2 = __float_as_uint(hrow[kf * 8 + 4]);
                unsigned a3 = __float_as_uint(hrow[kf * 8 + 8 * HP + 4]);
                #pragma unroll
                for (int q = 0; q < 4; q++) {
                    float2 bv = wb[(q * 32 + kf) * 32];
                    mma8(d[q], a0, a1, a2, a3, __float_as_uint(bv.x), __float_as_uint(bv.y));
                }
            }
            int rl = mwp * 16 + gid;
            #pragma unroll
            for (int q = 0; q < 4; q++) {
                int n0 = (nwp * 4 + q) * 8 + 2 * tig;
                float bv0 = __ldg(bl + n0), bv1 = __ldg(bl + n0 + 1);
                size_t base = (size_t)(b0 + rl) * (T_ * NTY) + (size_t)tt * NTY + n0;
                *(float2*)(intens + base) =
                    make_float2(softplusf(d[q][0] + bv0), softplusf(d[q][1] + bv1));
                size_t base2 = base + (size_t)8 * (T_ * NTY);
                *(float2*)(intens + base2) =
                    make_float2(softplusf(d[q][2] + bv0), softplusf(d[q][3] + bv1));
            }
            __syncthreads();
        }
    }
}

extern "C" void kernel_launch(void* const* d_in, const int* in_sizes, int n_in,
                              void* d_out, int out_size) {
    const int*   types = (const int*)d_in[0];
    const float* dtime = (const float*)d_in[1];
    const float* emb   = (const float*)d_in[2];
    const float* Wc    = (const float*)d_in[3];
    const float* bc    = (const float*)d_in[4];
    const float* Wl    = (const float*)d_in[5];
    const float* bl    = (const float*)d_in[6];
    cudaFuncSetAttribute(ctlstm_kernel, cudaFuncAttributeMaxDynamicSharedMemorySize, SMEM_BYTES);
    ctlstm_kernel<<<NBLK, TB, SMEM_BYTES>>>(types, dtime, emb, Wc, bc, Wl, bl, (float*)d_out);
}